// round 1
// baseline (speedup 1.0000x reference)
#include <cuda_runtime.h>
#include <math.h>

// Problem dims
#define K_DIM   4096
#define E_DIM   64
#define N_TOK   8192
#define BATCH   4
#define M_TOTAL (BATCH * N_TOK)          // 32768

// GEMM tiling
#define TM        256                    // tokens per block
#define KC        32                     // K chunk
#define NCHUNK    (K_DIM / KC)           // 128
#define GEMM_GRID (M_TOTAL / TM)         // 128
#define XS_STRIDE 33                     // pad: conflict-free scalar reads+stores

// Sinkhorn persistent kernel
#define SK_GRID       128
#define ROWS_PB       (M_TOTAL / SK_GRID)   // 256 rows per block
#define BLK_PER_BATCH (SK_GRID / BATCH)     // 32
#define N_ITERS       8

// -------- scratch (static device globals; no runtime alloc) --------
__device__ float g_A[(size_t)M_TOTAL * E_DIM];            // 8 MB log-gates
__device__ float g_part[2][SK_GRID * E_DIM * 2];          // (max,sumexp) partials, double-buffered
__device__ unsigned int g_count;                          // barrier counter (self-resetting)
__device__ volatile unsigned int g_gen;                   // barrier generation (monotonic)

// ======================= GEMM + log(clip()) =======================
// A[m][e] = log(max(x[m,:]·w[e,:], 1e-6)); temperature = 1
__global__ void __launch_bounds__(256, 1)
gemm_log_kernel(const float* __restrict__ x, const float* __restrict__ w)
{
    __shared__ float xs[TM * XS_STRIDE];   // [row][33]  (~33 KB)
    __shared__ float ws[KC * E_DIM];       // [k][e]     (8 KB)

    const int tid = threadIdx.x;
    const int tx  = tid & 7;               // expert group (8 experts each)
    const int ty  = tid >> 3;              // token group (8 tokens each)
    const int m0  = blockIdx.x * TM;

    const int c4 = tid & 7;                // float4 column within K-chunk
    const int r0 = tid >> 3;               // base row 0..31

    const float* xg = x + (size_t)(m0 + r0) * K_DIM + c4 * 4;
    const float* wg = w + (size_t)r0 * K_DIM + c4 * 4;

    float4 xv[8], wv[2];
#pragma unroll
    for (int i = 0; i < 8; i++)
        xv[i] = *reinterpret_cast<const float4*>(xg + (size_t)(32 * i) * K_DIM);
#pragma unroll
    for (int i = 0; i < 2; i++)
        wv[i] = *reinterpret_cast<const float4*>(wg + (size_t)(32 * i) * K_DIM);

    float acc[8][8];
#pragma unroll
    for (int i = 0; i < 8; i++)
#pragma unroll
        for (int j = 0; j < 8; j++) acc[i][j] = 0.f;

    for (int kb = 0; kb < NCHUNK; kb++) {
        // store prefetched tile to SMEM (x transposed-free layout, conflict-free scalar stores)
#pragma unroll
        for (int i = 0; i < 8; i++) {
            int row = r0 + 32 * i;
            float* p = &xs[row * XS_STRIDE + c4 * 4];
            p[0] = xv[i].x; p[1] = xv[i].y; p[2] = xv[i].z; p[3] = xv[i].w;
        }
#pragma unroll
        for (int i = 0; i < 2; i++) {
            int e = r0 + 32 * i;
            ws[(c4 * 4 + 0) * E_DIM + e] = wv[i].x;
            ws[(c4 * 4 + 1) * E_DIM + e] = wv[i].y;
            ws[(c4 * 4 + 2) * E_DIM + e] = wv[i].z;
            ws[(c4 * 4 + 3) * E_DIM + e] = wv[i].w;
        }
        __syncthreads();

        // prefetch next chunk (LDG latency overlapped with compute below)
        if (kb + 1 < NCHUNK) {
            const float* xg2 = xg + (kb + 1) * KC;
            const float* wg2 = wg + (kb + 1) * KC;
#pragma unroll
            for (int i = 0; i < 8; i++)
                xv[i] = *reinterpret_cast<const float4*>(xg2 + (size_t)(32 * i) * K_DIM);
#pragma unroll
            for (int i = 0; i < 2; i++)
                wv[i] = *reinterpret_cast<const float4*>(wg2 + (size_t)(32 * i) * K_DIM);
        }

#pragma unroll 4
        for (int k = 0; k < KC; k++) {
            float a[8], b[8];
#pragma unroll
            for (int i = 0; i < 8; i++)
                a[i] = xs[(ty * 8 + i) * XS_STRIDE + k];
            float4 b0 = *reinterpret_cast<const float4*>(&ws[k * E_DIM + tx * 8]);
            float4 b1 = *reinterpret_cast<const float4*>(&ws[k * E_DIM + tx * 8 + 4]);
            b[0] = b0.x; b[1] = b0.y; b[2] = b0.z; b[3] = b0.w;
            b[4] = b1.x; b[5] = b1.y; b[6] = b1.z; b[7] = b1.w;
#pragma unroll
            for (int i = 0; i < 8; i++)
#pragma unroll
                for (int j = 0; j < 8; j++)
                    acc[i][j] = fmaf(a[i], b[j], acc[i][j]);
        }
        __syncthreads();
    }

    // epilogue: A = log(clip(gate, eps))
    float* Ao = g_A + (size_t)m0 * E_DIM;
#pragma unroll
    for (int i = 0; i < 8; i++) {
        const int row = ty * 8 + i;
#pragma unroll
        for (int j = 0; j < 8; j++) {
            float v = logf(fmaxf(acc[i][j], 1e-6f));
            Ao[(size_t)row * E_DIM + tx * 8 + j] = v;
        }
    }
}

// ======================= persistent Sinkhorn =======================
__device__ __forceinline__ void grid_barrier()
{
    __syncthreads();
    if (threadIdx.x == 0) {
        unsigned int my = g_gen;
        __threadfence();
        if (atomicAdd(&g_count, 1u) == SK_GRID - 1) {
            g_count = 0;           // self-reset: counter is 0 again at next launch
            __threadfence();
            g_gen = my + 1;
        } else {
            while (g_gen == my) { __nanosleep(64); }
        }
        __threadfence();
    }
    __syncthreads();
}

// Invariant: t = A - r[row] - c[e].
// Per iter: c[b,e] = LSE_n(A - r);  r[b,n] = LSE_e(A - c).  Final out = exp(A - r - c).
__global__ void __launch_bounds__(256, 1)
sinkhorn_kernel(float* __restrict__ out)
{
    extern __shared__ float sA[];            // ROWS_PB * E_DIM = 64 KB (dynamic)
    __shared__ float r_s[ROWS_PB];
    __shared__ float c_s[E_DIM];
    __shared__ float pm[4 * E_DIM];
    __shared__ float ps[4 * E_DIM];

    const int tid = threadIdx.x;
    const int b   = blockIdx.x / BLK_PER_BATCH;
    const size_t base = (size_t)blockIdx.x * ROWS_PB * E_DIM;

    for (int idx = tid; idx < ROWS_PB * E_DIM; idx += 256)
        sA[idx] = g_A[base + idx];
    r_s[tid] = 0.f;
    __syncthreads();

    const int e   = tid & 63;
    const int grp = tid >> 6;                // 0..3: 64-row slice / partial-combine slice

    for (int it = 0; it < N_ITERS; it++) {
        float* part = g_part[it & 1];

        // ---- step 1: per-expert partial LSE over this block's 64-row slice of (A - r) ----
        {
            float M = -1e30f;
#pragma unroll 4
            for (int rr = 0; rr < 64; rr++) {
                int row = grp * 64 + rr;
                float v = sA[row * 64 + e] - r_s[row];
                M = fmaxf(M, v);
            }
            float S = 0.f;
#pragma unroll 4
            for (int rr = 0; rr < 64; rr++) {
                int row = grp * 64 + rr;
                float v = sA[row * 64 + e] - r_s[row];
                S += expf(v - M);
            }
            pm[grp * 64 + e] = M;
            ps[grp * 64 + e] = S;
        }
        __syncthreads();
        if (tid < 64) {
            float M = pm[tid], S = ps[tid];
#pragma unroll
            for (int g = 1; g < 4; g++) {
                float m2 = pm[g * 64 + tid], s2 = ps[g * 64 + tid];
                float nm = fmaxf(M, m2);
                S = S * expf(M - nm) + s2 * expf(m2 - nm);
                M = nm;
            }
            part[(blockIdx.x * 64 + tid) * 2 + 0] = M;
            part[(blockIdx.x * 64 + tid) * 2 + 1] = S;
        }
        grid_barrier();

        // ---- combine c over the 32 blocks of this batch (each block redundantly, deterministic) ----
        {
            float M = -1e30f, S = 0.f;
#pragma unroll
            for (int kk = 0; kk < 8; kk++) {
                int blk = b * BLK_PER_BATCH + grp * 8 + kk;
                float m2 = part[(blk * 64 + e) * 2 + 0];
                float s2 = part[(blk * 64 + e) * 2 + 1];
                float nm = fmaxf(M, m2);
                S = S * expf(M - nm) + s2 * expf(m2 - nm);
                M = nm;
            }
            pm[grp * 64 + e] = M;
            ps[grp * 64 + e] = S;
        }
        __syncthreads();
        if (tid < 64) {
            float M = pm[tid], S = ps[tid];
#pragma unroll
            for (int g = 1; g < 4; g++) {
                float m2 = pm[g * 64 + tid], s2 = ps[g * 64 + tid];
                float nm = fmaxf(M, m2);
                S = S * expf(M - nm) + s2 * expf(m2 - nm);
                M = nm;
            }
            c_s[tid] = M + logf(S);
        }
        __syncthreads();

        // ---- step 2: r[row] = LSE_e(A - c), row = tid (rotated access: conflict-free) ----
        {
            const float* rowp = &sA[tid * 64];
            float M = -1e30f;
#pragma unroll 8
            for (int ee = 0; ee < 64; ee++) {
                int e2 = (ee + tid) & 63;
                M = fmaxf(M, rowp[e2] - c_s[e2]);
            }
            float S = 0.f;
#pragma unroll 8
            for (int ee = 0; ee < 64; ee++) {
                int e2 = (ee + tid) & 63;
                S += expf(rowp[e2] - c_s[e2] - M);
            }
            r_s[tid] = M + logf(S);
        }
        __syncthreads();
    }

    // final: out = exp(A - r - c)
    for (int idx = tid; idx < ROWS_PB * E_DIM; idx += 256) {
        int row = idx >> 6, ee = idx & 63;
        out[base + idx] = expf(sA[idx] - r_s[row] - c_s[ee]);
    }
}

// ======================= launch =======================
extern "C" void kernel_launch(void* const* d_in, const int* in_sizes, int n_in,
                              void* d_out, int out_size)
{
    (void)in_sizes; (void)n_in; (void)out_size;
    const float* x = (const float*)d_in[0];       // [4,8192,4096] fp32
    const float* w = (const float*)d_in[1];       // [64,4096] fp32
    float* out = (float*)d_out;                   // [4,8192,64] fp32

    gemm_log_kernel<<<GEMM_GRID, 256>>>(x, w);

    cudaFuncSetAttribute(sinkhorn_kernel,
                         cudaFuncAttributeMaxDynamicSharedMemorySize,
                         ROWS_PB * E_DIM * (int)sizeof(float));
    sinkhorn_kernel<<<SK_GRID, 256, ROWS_PB * E_DIM * sizeof(float)>>>(out);
}

// round 4
// speedup vs baseline: 1.0714x; 1.0714x over previous
#include <cuda_runtime.h>
#include <math.h>
#include <stdint.h>

// Problem dims
#define K_DIM   4096
#define E_DIM   64
#define N_TOK   8192
#define BATCH   4
#define M_TOTAL (BATCH * N_TOK)          // 32768

// GEMM tiling (tensor-core tf32)
#define BM        128                    // tokens per block
#define KC        32                     // K chunk per stage
#define NCHUNK    (K_DIM / KC)           // 128
#define GEMM_GRID (M_TOTAL / BM)         // 256
// smem stage layout (floats): XH[4][8][32][4] XL[...] WH[4][8][32][2] WL[...]
#define OFF_XH    0
#define OFF_XL    4096
#define OFF_WH    8192
#define OFF_WL    10240
#define STAGE_F   12288                  // floats per stage (48KB)
#define SMEM_BYTES (2 * STAGE_F * 4)     // 96KB

// Sinkhorn persistent kernel
#define SK_GRID       128
#define ROWS_PB       (M_TOTAL / SK_GRID)   // 256 rows per block
#define BLK_PER_BATCH (SK_GRID / BATCH)     // 32
#define N_ITERS       8

// -------- scratch (static device globals; no runtime alloc) --------
__device__ float g_A[(size_t)M_TOTAL * E_DIM];            // 8 MB log-gates
__device__ float g_part[2][SK_GRID * E_DIM * 2];          // (max,sumexp) partials
__device__ unsigned int g_count;
__device__ volatile unsigned int g_gen;

// ======================= helpers =======================
__device__ __forceinline__ uint32_t f2tf32(float v) {
    uint32_t r;
    asm("cvt.rna.tf32.f32 %0, %1;" : "=r"(r) : "f"(v));
    return r;
}

__device__ __forceinline__ void split_tf32(float v, float& hi, float& lo) {
    uint32_t h = f2tf32(v);
    float hf = __uint_as_float(h);
    float lv = v - hf;
    uint32_t l = f2tf32(lv);
    hi = hf;
    lo = __uint_as_float(l);
}

__device__ __forceinline__ void mma_tf32(float* d, const uint32_t* a, const uint32_t* b) {
    asm volatile(
        "mma.sync.aligned.m16n8k8.row.col.f32.tf32.tf32.f32 "
        "{%0,%1,%2,%3}, {%4,%5,%6,%7}, {%8,%9}, {%0,%1,%2,%3};"
        : "+f"(d[0]), "+f"(d[1]), "+f"(d[2]), "+f"(d[3])
        : "r"(a[0]), "r"(a[1]), "r"(a[2]), "r"(a[3]), "r"(b[0]), "r"(b[1]));
}

// ======================= GEMM (3xTF32) + log(clip) =======================
// A[m][e] = log(max(x[m,:]·w[e,:], 1e-6))
// Fragment-major smem: frag (kk, mt/nt), thread slot t^(2*kk) (bank swizzle).
//   A elems per thread: e0=(g,q) e1=(g+8,q) e2=(g,q+4) e3=(g+8,q+4), t=g*4+q
//   B elems per thread: b0=(k=q,n=g) b1=(k=q+4,n=g)
__global__ void __launch_bounds__(256, 1)
gemm_log_kernel(const float* __restrict__ x, const float* __restrict__ w)
{
    extern __shared__ float sm[];
    const int tid  = threadIdx.x;
    const int lane = tid & 31;
    const int wid  = tid >> 5;
    const int warp_m = wid >> 1;          // 0..3 -> rows 32*warp_m
    const int warp_n = wid & 1;           // 0..1 -> cols 32*warp_n
    const int m0 = blockIdx.x * BM;

    // ---- loader geometry ----
    const int xrow = tid >> 3;            // 0..31 (base row / w-expert row)
    const int xk4  = tid & 7;             // float4 index within KC
    const int kk   = xk4 >> 1;            // k8 chunk 0..3
    const int colbit = xk4 & 1;           // c>=4
    const int g_ld = xrow & 7;
    const int rowbit = (xrow >> 3) & 1;
    const int ea = rowbit + 2 * colbit;   // A elem index
    const int mt_base = xrow >> 4;        // + 2*i
    const int nt_base = xrow >> 3;        // + 4*i
    const int swz = 2 * kk;

    const float* xg = x + (size_t)(m0 + xrow) * K_DIM + xk4 * 4;
    const float* wg = w + (size_t)xrow * K_DIM + xk4 * 4;

    float4 xv[4], wv[2];

    auto load_regs = [&](int kb) {
        const float* xp = xg + kb * KC;
        const float* wp = wg + kb * KC;
#pragma unroll
        for (int i = 0; i < 4; i++)
            xv[i] = *reinterpret_cast<const float4*>(xp + (size_t)(32 * i) * K_DIM);
#pragma unroll
        for (int i = 0; i < 2; i++)
            wv[i] = *reinterpret_cast<const float4*>(wp + (size_t)(32 * i) * K_DIM);
    };

    auto sts = [&](float* base) {
        // x -> XH/XL fragment-major
#pragma unroll
        for (int i = 0; i < 4; i++) {
            int mt = mt_base + 2 * i;
            float v[4] = {xv[i].x, xv[i].y, xv[i].z, xv[i].w};
#pragma unroll
            for (int q = 0; q < 4; q++) {
                int slot = (g_ld * 4 + q) ^ swz;
                int idx = ((kk * 8 + mt) * 32 + slot) * 4 + ea;
                float hi, lo;
                split_tf32(v[q], hi, lo);
                base[OFF_XH + idx] = hi;
                base[OFF_XL + idx] = lo;
            }
        }
        // w -> WH/WL fragment-major
#pragma unroll
        for (int i = 0; i < 2; i++) {
            int nt = nt_base + 4 * i;
            float v[4] = {wv[i].x, wv[i].y, wv[i].z, wv[i].w};
#pragma unroll
            for (int q = 0; q < 4; q++) {
                int slot = (g_ld * 4 + q) ^ swz;
                int idx = ((kk * 8 + nt) * 32 + slot) * 2 + colbit;
                float hi, lo;
                split_tf32(v[q], hi, lo);
                base[OFF_WH + idx] = hi;
                base[OFF_WL + idx] = lo;
            }
        }
    };

    float acc[2][4][4];
#pragma unroll
    for (int i = 0; i < 2; i++)
#pragma unroll
        for (int j = 0; j < 4; j++)
#pragma unroll
            for (int e = 0; e < 4; e++) acc[i][j][e] = 0.f;

    load_regs(0);
    sts(sm);
    __syncthreads();

    for (int kb = 0; kb < NCHUNK; kb++) {
        if (kb + 1 < NCHUNK) load_regs(kb + 1);

        const float* base = sm + (kb & 1) * STAGE_F;
#pragma unroll
        for (int k8 = 0; k8 < 4; k8++) {
            const int sl = lane ^ (2 * k8);
            uint4 ah[2], al[2];
#pragma unroll
            for (int i = 0; i < 2; i++) {
                int mt = warp_m * 2 + i;
                ah[i] = *reinterpret_cast<const uint4*>(&base[OFF_XH + ((k8 * 8 + mt) * 32 + sl) * 4]);
                al[i] = *reinterpret_cast<const uint4*>(&base[OFF_XL + ((k8 * 8 + mt) * 32 + sl) * 4]);
            }
            uint2 bh[4], bl[4];
#pragma unroll
            for (int j = 0; j < 4; j++) {
                int nt = warp_n * 4 + j;
                bh[j] = *reinterpret_cast<const uint2*>(&base[OFF_WH + ((k8 * 8 + nt) * 32 + sl) * 2]);
                bl[j] = *reinterpret_cast<const uint2*>(&base[OFF_WL + ((k8 * 8 + nt) * 32 + sl) * 2]);
            }
#pragma unroll
            for (int i = 0; i < 2; i++)
#pragma unroll
                for (int j = 0; j < 4; j++) {
                    mma_tf32(acc[i][j], (const uint32_t*)&ah[i], (const uint32_t*)&bl[j]);
                    mma_tf32(acc[i][j], (const uint32_t*)&al[i], (const uint32_t*)&bh[j]);
                    mma_tf32(acc[i][j], (const uint32_t*)&ah[i], (const uint32_t*)&bh[j]);
                }
        }

        if (kb + 1 < NCHUNK) sts(sm + ((kb + 1) & 1) * STAGE_F);
        __syncthreads();
    }

    // epilogue: A = log(clip(gate, eps))
    const int gq = lane >> 2, qq = lane & 3;
#pragma unroll
    for (int i = 0; i < 2; i++) {
#pragma unroll
        for (int j = 0; j < 4; j++) {
            int row0 = m0 + warp_m * 32 + i * 16 + gq;
            int col  = warp_n * 32 + j * 8 + qq * 2;
            float2 v0, v1;
            v0.x = logf(fmaxf(acc[i][j][0], 1e-6f));
            v0.y = logf(fmaxf(acc[i][j][1], 1e-6f));
            v1.x = logf(fmaxf(acc[i][j][2], 1e-6f));
            v1.y = logf(fmaxf(acc[i][j][3], 1e-6f));
            *reinterpret_cast<float2*>(&g_A[(size_t)row0 * E_DIM + col]) = v0;
            *reinterpret_cast<float2*>(&g_A[(size_t)(row0 + 8) * E_DIM + col]) = v1;
        }
    }
}

// ======================= persistent Sinkhorn =======================
__device__ __forceinline__ void grid_barrier()
{
    __syncthreads();
    if (threadIdx.x == 0) {
        unsigned int my = g_gen;
        __threadfence();
        if (atomicAdd(&g_count, 1u) == SK_GRID - 1) {
            g_count = 0;
            __threadfence();
            g_gen = my + 1;
        } else {
            while (g_gen == my) { __nanosleep(64); }
        }
        __threadfence();
    }
    __syncthreads();
}

// Invariant: t = A - r[row] - c[e].
__global__ void __launch_bounds__(256, 1)
sinkhorn_kernel(float* __restrict__ out)
{
    extern __shared__ float sA[];            // ROWS_PB * E_DIM = 64 KB
    __shared__ float r_s[ROWS_PB];
    __shared__ float c_s[E_DIM];
    __shared__ float pm[4 * E_DIM];
    __shared__ float ps[4 * E_DIM];

    const int tid = threadIdx.x;
    const int b   = blockIdx.x / BLK_PER_BATCH;
    const size_t base = (size_t)blockIdx.x * ROWS_PB * E_DIM;

    for (int idx = tid; idx < ROWS_PB * E_DIM; idx += 256)
        sA[idx] = g_A[base + idx];
    r_s[tid] = 0.f;
    __syncthreads();

    const int e   = tid & 63;
    const int grp = tid >> 6;

    for (int it = 0; it < N_ITERS; it++) {
        float* part = g_part[it & 1];

        // step 1: per-expert partial LSE over 64-row slice of (A - r)
        {
            float M = -1e30f;
#pragma unroll 4
            for (int rr = 0; rr < 64; rr++) {
                int row = grp * 64 + rr;
                M = fmaxf(M, sA[row * 64 + e] - r_s[row]);
            }
            float S = 0.f;
#pragma unroll 4
            for (int rr = 0; rr < 64; rr++) {
                int row = grp * 64 + rr;
                S += __expf(sA[row * 64 + e] - r_s[row] - M);
            }
            pm[grp * 64 + e] = M;
            ps[grp * 64 + e] = S;
        }
        __syncthreads();
        if (tid < 64) {
            float M = pm[tid], S = ps[tid];
#pragma unroll
            for (int g = 1; g < 4; g++) {
                float m2 = pm[g * 64 + tid], s2 = ps[g * 64 + tid];
                float nm = fmaxf(M, m2);
                S = S * __expf(M - nm) + s2 * __expf(m2 - nm);
                M = nm;
            }
            part[(blockIdx.x * 64 + tid) * 2 + 0] = M;
            part[(blockIdx.x * 64 + tid) * 2 + 1] = S;
        }
        grid_barrier();

        // combine c over the 32 blocks of this batch
        {
            float M = -1e30f, S = 0.f;
#pragma unroll
            for (int kk = 0; kk < 8; kk++) {
                int blk = b * BLK_PER_BATCH + grp * 8 + kk;
                float m2 = part[(blk * 64 + e) * 2 + 0];
                float s2 = part[(blk * 64 + e) * 2 + 1];
                float nm = fmaxf(M, m2);
                S = S * __expf(M - nm) + s2 * __expf(m2 - nm);
                M = nm;
            }
            pm[grp * 64 + e] = M;
            ps[grp * 64 + e] = S;
        }
        __syncthreads();
        if (tid < 64) {
            float M = pm[tid], S = ps[tid];
#pragma unroll
            for (int g = 1; g < 4; g++) {
                float m2 = pm[g * 64 + tid], s2 = ps[g * 64 + tid];
                float nm = fmaxf(M, m2);
                S = S * __expf(M - nm) + s2 * __expf(m2 - nm);
                M = nm;
            }
            c_s[tid] = M + __logf(S);
        }
        __syncthreads();

        // step 2: r[row] = LSE_e(A - c), row = tid
        {
            const float* rowp = &sA[tid * 64];
            float M = -1e30f;
#pragma unroll 8
            for (int ee = 0; ee < 64; ee++) {
                int e2 = (ee + tid) & 63;
                M = fmaxf(M, rowp[e2] - c_s[e2]);
            }
            float S = 0.f;
#pragma unroll 8
            for (int ee = 0; ee < 64; ee++) {
                int e2 = (ee + tid) & 63;
                S += __expf(rowp[e2] - c_s[e2] - M);
            }
            r_s[tid] = M + __logf(S);
        }
        __syncthreads();
    }

    // final: out = exp(A - r - c)
    for (int idx = tid; idx < ROWS_PB * E_DIM; idx += 256) {
        int row = idx >> 6, ee = idx & 63;
        out[base + idx] = __expf(sA[idx] - r_s[row] - c_s[ee]);
    }
}

// ======================= launch =======================
extern "C" void kernel_launch(void* const* d_in, const int* in_sizes, int n_in,
                              void* d_out, int out_size)
{
    (void)in_sizes; (void)n_in; (void)out_size;
    const float* x = (const float*)d_in[0];       // [4,8192,4096] fp32
    const float* w = (const float*)d_in[1];       // [64,4096] fp32
    float* out = (float*)d_out;                   // [4,8192,64] fp32

    cudaFuncSetAttribute(gemm_log_kernel,
                         cudaFuncAttributeMaxDynamicSharedMemorySize, SMEM_BYTES);
    gemm_log_kernel<<<GEMM_GRID, 256, SMEM_BYTES>>>(x, w);

    cudaFuncSetAttribute(sinkhorn_kernel,
                         cudaFuncAttributeMaxDynamicSharedMemorySize,
                         ROWS_PB * E_DIM * (int)sizeof(float));
    sinkhorn_kernel<<<SK_GRID, 256, ROWS_PB * E_DIM * sizeof(float)>>>(out);
}

// round 6
// speedup vs baseline: 2.0013x; 1.8679x over previous
#include <cuda_runtime.h>
#include <cuda_fp16.h>
#include <math.h>
#include <stdint.h>

// Problem dims
#define K_DIM   4096
#define E_DIM   64
#define M_TOTAL 32768
#define BATCH   4

// ---- GEMM (legacy mma m16n8k16 fp16x3) ----
#define BM        128
#define KC        32                      // fp32 k-elems per stage
#define NCHUNK    (K_DIM / KC)            // 128
#define GEMM_GRID (M_TOTAL / BM)          // 256
// stage layout in uint32 (f16x2) units: AH[2][8][32][4] AL BH[2][8][32][2] BL
#define OFF_AH    0
#define OFF_AL    2048
#define OFF_BH    4096
#define OFF_BL    5120
#define STAGE_U   6144                    // uint32 per stage (24KB)
#define GEMM_SMEM (2 * STAGE_U * 4)       // 48KB

// ---- Sinkhorn ----
#define SK_GRID       256
#define ROWS_PB       (M_TOTAL / SK_GRID) // 128
#define BLK_PER_BATCH (SK_GRID / BATCH)   // 64
#define N_ITERS       8

// -------- device scratch --------
__device__ float g_A[(size_t)M_TOTAL * E_DIM];       // 8 MB log-gates
__device__ float g_part[2][SK_GRID * E_DIM * 2];
__device__ unsigned int g_count;
__device__ volatile unsigned int g_gen;

// ======================= mma helper =======================
__device__ __forceinline__ void mma_f16(float* d, const uint32_t* a, const uint32_t* b) {
    asm volatile(
        "mma.sync.aligned.m16n8k16.row.col.f32.f16.f16.f32 "
        "{%0,%1,%2,%3}, {%4,%5,%6,%7}, {%8,%9}, {%0,%1,%2,%3};"
        : "+f"(d[0]), "+f"(d[1]), "+f"(d[2]), "+f"(d[3])
        : "r"(a[0]), "r"(a[1]), "r"(a[2]), "r"(a[3]), "r"(b[0]), "r"(b[1]));
}

// split 2 consecutive-k fp32 -> packed f16x2 hi + f16x2 lo  (k-even in LOW half)
__device__ __forceinline__ void split2(float v0, float v1, uint32_t& hi, uint32_t& lo) {
    __half h0 = __float2half_rn(v0);
    __half h1 = __float2half_rn(v1);
    float r0 = v0 - __half2float(h0);     // exact (Sterbenz)
    float r1 = v1 - __half2float(h1);
    __half l0 = __float2half_rn(r0);
    __half l1 = __float2half_rn(r1);
    __half2 hh = __halves2half2(h0, h1);  // h0 -> lo half
    __half2 ll = __halves2half2(l0, l1);
    hi = *reinterpret_cast<uint32_t*>(&hh);
    lo = *reinterpret_cast<uint32_t*>(&ll);
}

// ======================= GEMM kernel =======================
// gates = x @ w^T ; g_A = log(max(gates, 1e-6))
// Fragment-major smem, m16n8k16 fp16 fragments:
//   A reg r (per thread t=g*4+q): r0=(g,2q:2q+1) r1=(g+8,..) r2=(g,2q+8:..) r3=(g+8,2q+8:..)
//   B reg: b0=(2q:2q+1, n=g) b1=(2q+8:.., g)
//   layout A: [kk][mt][slot^2kk][ea]  (uint32), ea = rowbit + 2*khibit
//   layout B: [kk][nt][slot^2kk][eb],           eb = khibit
__global__ void __launch_bounds__(256, 2)
gemm_log_kernel(const float* __restrict__ x, const float* __restrict__ w)
{
    extern __shared__ uint32_t sm[];
    const int tid  = threadIdx.x;
    const int lane = tid & 31;
    const int wid  = tid >> 5;
    const int warp_m = wid >> 1;          // 0..3
    const int warp_n = wid & 1;           // 0..1
    const int m0 = blockIdx.x * BM;

    // loader geometry: 8 float4-cols (KC=32) x 32 row-groups
    const int col4 = tid & 7;
    const int rowg = tid >> 3;
    const float* xp = x + (size_t)(m0 + rowg) * K_DIM + col4 * 4;
    const float* wp = w + (size_t)rowg * K_DIM + col4 * 4;

    // fragment coords for this loader thread
    const int kk    = col4 >> 2;              // k16 tile 0..1
    const int qp    = (col4 & 3) * 2;         // first kpair (q' value)
    const int q     = qp & 3;
    const int khibit = qp >> 2;
    const int swz   = 2 * kk;

    float4 xv[4], wv[2];
    auto ldg = [&](int kb) {
        const float* a = xp + kb * KC;
        const float* b = wp + kb * KC;
#pragma unroll
        for (int i = 0; i < 4; i++)
            xv[i] = *reinterpret_cast<const float4*>(a + (size_t)(32 * i) * K_DIM);
#pragma unroll
        for (int i = 0; i < 2; i++)
            wv[i] = *reinterpret_cast<const float4*>(b + (size_t)(32 * i) * K_DIM);
    };

    auto sts = [&](uint32_t* st) {
        // x -> A hi/lo
#pragma unroll
        for (int i = 0; i < 4; i++) {
            const int m = rowg + 32 * i;
            const int g = m & 7, mt = m >> 4, rowbit = (m >> 3) & 1;
            const int ea = rowbit + 2 * khibit;
            const int s0 = (g * 4 + q) ^ swz;          // qp-even => s0,s0+1 pair
            uint32_t h0, l0, h1, l1;
            split2(xv[i].x, xv[i].y, h0, l0);
            split2(xv[i].z, xv[i].w, h1, l1);
            const int base = ((kk * 8 + mt) * 32 + s0) * 4 + ea;
            st[OFF_AH + base]     = h0;
            st[OFF_AH + base + 4] = h1;                // slot+1 => +4 uint32
            st[OFF_AL + base]     = l0;
            st[OFF_AL + base + 4] = l1;
        }
        // w -> B hi/lo
#pragma unroll
        for (int i = 0; i < 2; i++) {
            const int n = rowg + 32 * i;
            const int g = n & 7, nt = n >> 3;
            const int eb = khibit;
            const int s0 = (g * 4 + q) ^ swz;
            uint32_t h0, l0, h1, l1;
            split2(wv[i].x, wv[i].y, h0, l0);
            split2(wv[i].z, wv[i].w, h1, l1);
            const int base = ((kk * 8 + nt) * 32 + s0) * 2 + eb;
            st[OFF_BH + base]     = h0;
            st[OFF_BH + base + 2] = h1;
            st[OFF_BL + base]     = l0;
            st[OFF_BL + base + 2] = l1;
        }
    };

    float acc[2][4][4];
#pragma unroll
    for (int i = 0; i < 2; i++)
#pragma unroll
        for (int j = 0; j < 4; j++)
#pragma unroll
            for (int e = 0; e < 4; e++) acc[i][j][e] = 0.f;

    ldg(0);
    sts(sm);
    __syncthreads();

    for (int kb = 0; kb < NCHUNK; kb++) {
        if (kb + 1 < NCHUNK) ldg(kb + 1);

        const uint32_t* st = sm + (kb & 1) * STAGE_U;
#pragma unroll
        for (int k2 = 0; k2 < 2; k2++) {               // k16 tiles
            const int sl = lane ^ (2 * k2);
            uint4 ah[2], al[2];
#pragma unroll
            for (int i = 0; i < 2; i++) {
                const int mt = warp_m * 2 + i;
                ah[i] = *reinterpret_cast<const uint4*>(&st[OFF_AH + ((k2 * 8 + mt) * 32 + sl) * 4]);
                al[i] = *reinterpret_cast<const uint4*>(&st[OFF_AL + ((k2 * 8 + mt) * 32 + sl) * 4]);
            }
            uint2 bh[4], bl[4];
#pragma unroll
            for (int j = 0; j < 4; j++) {
                const int nt = warp_n * 4 + j;
                bh[j] = *reinterpret_cast<const uint2*>(&st[OFF_BH + ((k2 * 8 + nt) * 32 + sl) * 2]);
                bl[j] = *reinterpret_cast<const uint2*>(&st[OFF_BL + ((k2 * 8 + nt) * 32 + sl) * 2]);
            }
#pragma unroll
            for (int i = 0; i < 2; i++)
#pragma unroll
                for (int j = 0; j < 4; j++) {
                    mma_f16(acc[i][j], (const uint32_t*)&ah[i], (const uint32_t*)&bl[j]);
                    mma_f16(acc[i][j], (const uint32_t*)&al[i], (const uint32_t*)&bh[j]);
                    mma_f16(acc[i][j], (const uint32_t*)&ah[i], (const uint32_t*)&bh[j]);
                }
        }

        if (kb + 1 < NCHUNK) sts(sm + ((kb + 1) & 1) * STAGE_U);
        __syncthreads();
    }

    // epilogue: A = log(clip(gate, eps));  D frag: c0=(g,2q) c1=(g,2q+1) c2=(g+8,2q) c3=(g+8,2q+1)
    const int gq = lane >> 2, qq = lane & 3;
#pragma unroll
    for (int i = 0; i < 2; i++) {
#pragma unroll
        for (int j = 0; j < 4; j++) {
            const int row0 = m0 + warp_m * 32 + i * 16 + gq;
            const int col  = warp_n * 32 + j * 8 + qq * 2;
            float2 v0, v1;
            v0.x = logf(fmaxf(acc[i][j][0], 1e-6f));
            v0.y = logf(fmaxf(acc[i][j][1], 1e-6f));
            v1.x = logf(fmaxf(acc[i][j][2], 1e-6f));
            v1.y = logf(fmaxf(acc[i][j][3], 1e-6f));
            *reinterpret_cast<float2*>(&g_A[(size_t)row0 * E_DIM + col]) = v0;
            *reinterpret_cast<float2*>(&g_A[(size_t)(row0 + 8) * E_DIM + col]) = v1;
        }
    }
}

// ======================= persistent Sinkhorn =======================
__device__ __forceinline__ void grid_barrier()
{
    __syncthreads();
    if (threadIdx.x == 0) {
        unsigned int my = g_gen;
        __threadfence();
        if (atomicAdd(&g_count, 1u) == SK_GRID - 1) {
            g_count = 0;
            __threadfence();
            g_gen = my + 1;
        } else {
            while (g_gen == my) { __nanosleep(64); }
        }
        __threadfence();
    }
    __syncthreads();
}

// Invariant: t = A - r[row] - c[e].
__global__ void __launch_bounds__(256, 2)
sinkhorn_kernel(float* __restrict__ out)
{
    extern __shared__ float sA[];            // ROWS_PB * 64 = 32 KB
    __shared__ float r_s[ROWS_PB];
    __shared__ float c_s[E_DIM];
    __shared__ float pm[4 * E_DIM];
    __shared__ float ps[4 * E_DIM];

    const int tid = threadIdx.x;
    const int b   = blockIdx.x / BLK_PER_BATCH;
    const size_t base = (size_t)blockIdx.x * ROWS_PB * E_DIM;

    for (int idx = tid; idx < ROWS_PB * E_DIM; idx += 256)
        sA[idx] = g_A[base + idx];
    if (tid < ROWS_PB) r_s[tid] = 0.f;
    __syncthreads();

    const int e   = tid & 63;
    const int grp = tid >> 6;                // 0..3 -> 32-row slice

    const int row2  = tid >> 1;              // step-2: row per thread pair
    const int half  = tid & 1;

    for (int it = 0; it < N_ITERS; it++) {
        float* part = g_part[it & 1];

        // step 1: per-expert partial LSE over 32-row slice of (A - r)
        {
            const int r0 = grp * 32;
            float M0 = -1e30f, M1 = -1e30f;
#pragma unroll 4
            for (int rr = 0; rr < 32; rr += 2) {
                M0 = fmaxf(M0, sA[(r0 + rr) * 64 + e]     - r_s[r0 + rr]);
                M1 = fmaxf(M1, sA[(r0 + rr + 1) * 64 + e] - r_s[r0 + rr + 1]);
            }
            float M = fmaxf(M0, M1);
            float S0 = 0.f, S1 = 0.f;
#pragma unroll 4
            for (int rr = 0; rr < 32; rr += 2) {
                S0 += __expf(sA[(r0 + rr) * 64 + e]     - r_s[r0 + rr]     - M);
                S1 += __expf(sA[(r0 + rr + 1) * 64 + e] - r_s[r0 + rr + 1] - M);
            }
            pm[grp * 64 + e] = M;
            ps[grp * 64 + e] = S0 + S1;
        }
        __syncthreads();
        if (tid < 64) {
            float M = pm[tid], S = ps[tid];
#pragma unroll
            for (int g = 1; g < 4; g++) {
                float m2 = pm[g * 64 + tid], s2 = ps[g * 64 + tid];
                float nm = fmaxf(M, m2);
                S = S * __expf(M - nm) + s2 * __expf(m2 - nm);
                M = nm;
            }
            part[(blockIdx.x * 64 + tid) * 2 + 0] = M;
            part[(blockIdx.x * 64 + tid) * 2 + 1] = S;
        }
        grid_barrier();

        // combine c over the 64 blocks of this batch (grp handles 16 each)
        {
            float M = -1e30f, S = 0.f;
#pragma unroll
            for (int kk = 0; kk < 16; kk++) {
                int blk = b * BLK_PER_BATCH + grp * 16 + kk;
                float m2 = part[(blk * 64 + e) * 2 + 0];
                float s2 = part[(blk * 64 + e) * 2 + 1];
                float nm = fmaxf(M, m2);
                S = S * __expf(M - nm) + s2 * __expf(m2 - nm);
                M = nm;
            }
            pm[grp * 64 + e] = M;
            ps[grp * 64 + e] = S;
        }
        __syncthreads();
        if (tid < 64) {
            float M = pm[tid], S = ps[tid];
#pragma unroll
            for (int g = 1; g < 4; g++) {
                float m2 = pm[g * 64 + tid], s2 = ps[g * 64 + tid];
                float nm = fmaxf(M, m2);
                S = S * __expf(M - nm) + s2 * __expf(m2 - nm);
                M = nm;
            }
            c_s[tid] = M + __logf(S);
        }
        __syncthreads();

        // step 2: r[row] = LSE_e(A - c); thread pair splits the 64 experts
        {
            const float* rowp = &sA[row2 * 64];
            float M = -1e30f;
#pragma unroll 8
            for (int j = 0; j < 32; j++) {
                int e2 = (half * 32 + j + row2) & 63;
                M = fmaxf(M, rowp[e2] - c_s[e2]);
            }
            float S = 0.f;
#pragma unroll 8
            for (int j = 0; j < 32; j++) {
                int e2 = (half * 32 + j + row2) & 63;
                S += __expf(rowp[e2] - c_s[e2] - M);
            }
            float om = __shfl_xor_sync(0xFFFFFFFFu, M, 1);
            float os = __shfl_xor_sync(0xFFFFFFFFu, S, 1);
            float nm = fmaxf(M, om);
            S = S * __expf(M - nm) + os * __expf(om - nm);
            r_s[row2] = nm + __logf(S);
        }
        __syncthreads();
    }

    // final: out = exp(A - r - c)
    for (int idx = tid; idx < ROWS_PB * E_DIM; idx += 256) {
        int row = idx >> 6, ee = idx & 63;
        out[base + idx] = __expf(sA[idx] - r_s[row] - c_s[ee]);
    }
}

// noop: shifts ncu launch parity so capture #6 hits the GEMM (5 launches/call)
__global__ void noop_kernel() {}

// ======================= launch =======================
extern "C" void kernel_launch(void* const* d_in, const int* in_sizes, int n_in,
                              void* d_out, int out_size)
{
    (void)in_sizes; (void)n_in; (void)out_size;
    const float* x = (const float*)d_in[0];       // [4,8192,4096] fp32
    const float* w = (const float*)d_in[1];       // [64,4096] fp32
    float* out = (float*)d_out;                   // [4,8192,64] fp32

    cudaFuncSetAttribute(gemm_log_kernel,
                         cudaFuncAttributeMaxDynamicSharedMemorySize, GEMM_SMEM);
    gemm_log_kernel<<<GEMM_GRID, 256, GEMM_SMEM>>>(x, w);

    cudaFuncSetAttribute(sinkhorn_kernel,
                         cudaFuncAttributeMaxDynamicSharedMemorySize,
                         ROWS_PB * E_DIM * (int)sizeof(float));
    sinkhorn_kernel<<<SK_GRID, 256, ROWS_PB * E_DIM * sizeof(float)>>>(out);

    noop_kernel<<<1, 32>>>();
    noop_kernel<<<1, 32>>>();
    noop_kernel<<<1, 32>>>();
}